// round 2
// baseline (speedup 1.0000x reference)
#include <cuda_runtime.h>
#include <math.h>

// Problem constants
#define BSZ   64
#define HDIM  4096
#define IDIM  14336
#define NLUT  4096
#define WSCALE 0.02f

// Tiling
#define BM 64
#define BN 64
#define BK 32
#define NTHREADS 128
#define PAD 2
#define LDS_W (BN + PAD)   // 66 -> <=2-way bank conflicts on transposed stores
#define LDS_X (BM + PAD)   // 66
#define SPLITK 8

// Scratch (static device arrays; no allocations allowed)
__device__ float d_xg[BSZ * HDIM];      // x * gate_sign_r * WSCALE
__device__ float d_ratio[HDIM];         // gate_sign_r * up_sign_r  (xu = xg * ratio)
__device__ float d_hd[BSZ * IDIM];      // silu(gate)*up * down_sign_r * WSCALE

// ---------- packed fp32x2 helpers (FFMA2: 2x fp32 throughput on sm_103a) ----------
__device__ __forceinline__ unsigned long long ffma2(unsigned long long a,
                                                    unsigned long long b,
                                                    unsigned long long c) {
    unsigned long long r;
    asm("fma.rn.f32x2 %0, %1, %2, %3;" : "=l"(r) : "l"(a), "l"(b), "l"(c));
    return r;
}
__device__ __forceinline__ unsigned long long pack2(float lo, float hi) {
    unsigned long long r;
    asm("mov.b64 %0, {%1, %2};" : "=l"(r) : "f"(lo), "f"(hi));
    return r;
}
__device__ __forceinline__ float2 unpack2(unsigned long long d) {
    float2 f;
    asm("mov.b64 {%0, %1}, %2;" : "=f"(f.x), "=f"(f.y) : "l"(d));
    return f;
}

// ---------- prep: xg = x * gsr * scale ; ratio = gsr * usr ----------
__global__ void prep_kernel(const float* __restrict__ x,
                            const float* __restrict__ gsr,
                            const float* __restrict__ usr) {
    int idx = blockIdx.x * blockDim.x + threadIdx.x;
    if (idx < BSZ * HDIM) {
        int h = idx & (HDIM - 1);
        d_xg[idx] = x[idx] * gsr[h] * WSCALE;
    }
    if (idx < HDIM) {
        d_ratio[idx] = gsr[idx] * usr[idx];
    }
}

// ---------- stage 1: fused gate+up dequant-GEMM + silu*mul epilogue ----------
// hd[b,i] = silu(gsl[i]*sum_h xg[b,h]*lutG[gw[i,h]])
//           * (usl[i]*sum_h xg[b,h]*ratio[h]*lutU[uw[i,h]]) * dsr[i] * WSCALE
__global__ __launch_bounds__(NTHREADS)
void gateup_kernel(const int* __restrict__ gwalks, const int* __restrict__ uwalks,
                   const float* __restrict__ lutg, const float* __restrict__ lutu,
                   const float* __restrict__ gsl, const float* __restrict__ usl,
                   const float* __restrict__ dsr) {
    extern __shared__ float smem[];
    float* sLutG = smem;                      // 4096
    float* sLutU = sLutG + NLUT;              // 4096
    float* sX    = sLutU + NLUT;              // BK*LDS_X
    float* sWg   = sX + BK * LDS_X;           // BK*LDS_W
    float* sWu   = sWg + BK * LDS_W;          // BK*LDS_W

    const int tid = threadIdx.x;

    // cooperative LUT load (float4)
    {
        const float4* lg4 = (const float4*)lutg;
        const float4* lu4 = (const float4*)lutu;
        float4* sg4 = (float4*)sLutG;
        float4* su4 = (float4*)sLutU;
#pragma unroll
        for (int r = 0; r < NLUT / 4 / NTHREADS; ++r) {
            sg4[tid + r * NTHREADS] = lg4[tid + r * NTHREADS];
            su4[tid + r * NTHREADS] = lu4[tid + r * NTHREADS];
        }
    }

    const int n0 = blockIdx.x * BN;
    const int tn = tid & 15;   // n = n0 + tn*4 .. +3
    const int tm = tid >> 4;   // b = tm*8 .. +7

    unsigned long long accg[8][2], accu[8][2];
#pragma unroll
    for (int m = 0; m < 8; ++m) {
        accg[m][0] = 0ull; accg[m][1] = 0ull;
        accu[m][0] = 0ull; accu[m][1] = 0ull;
    }

    for (int k0 = 0; k0 < HDIM; k0 += BK) {
        __syncthreads();  // smem reuse barrier (also orders LUT load on iter 0)

        // X tile (64 x 32) -> sX[k][m] transposed
#pragma unroll
        for (int r = 0; r < 4; ++r) {
            int idx = tid + r * NTHREADS;       // 0..511
            int m   = idx >> 3;                 // 0..63
            int kq  = (idx & 7) << 2;           // 0..28
            float4 v = *(const float4*)(d_xg + m * HDIM + k0 + kq);
            sX[(kq + 0) * LDS_X + m] = v.x;
            sX[(kq + 1) * LDS_X + m] = v.y;
            sX[(kq + 2) * LDS_X + m] = v.z;
            sX[(kq + 3) * LDS_X + m] = v.w;
        }

        // dequant gate & up walks tiles (64 x 32) -> sW[k][n]
#pragma unroll
        for (int r = 0; r < 4; ++r) {
            int idx = tid + r * NTHREADS;
            int row = idx >> 3;                 // n local
            int kq  = (idx & 7) << 2;           // k local
            int4 wg = *(const int4*)(gwalks + (size_t)(n0 + row) * HDIM + k0 + kq);
            sWg[(kq + 0) * LDS_W + row] = sLutG[wg.x];
            sWg[(kq + 1) * LDS_W + row] = sLutG[wg.y];
            sWg[(kq + 2) * LDS_W + row] = sLutG[wg.z];
            sWg[(kq + 3) * LDS_W + row] = sLutG[wg.w];
            int4 wu = *(const int4*)(uwalks + (size_t)(n0 + row) * HDIM + k0 + kq);
            float4 rr = *(const float4*)(d_ratio + k0 + kq);
            sWu[(kq + 0) * LDS_W + row] = sLutU[wu.x] * rr.x;
            sWu[(kq + 1) * LDS_W + row] = sLutU[wu.y] * rr.y;
            sWu[(kq + 2) * LDS_W + row] = sLutU[wu.z] * rr.z;
            sWu[(kq + 3) * LDS_W + row] = sLutU[wu.w] * rr.w;
        }
        __syncthreads();

#pragma unroll 4
        for (int k = 0; k < BK; ++k) {
            const float2* xrow = (const float2*)(sX + k * LDS_X + tm * 8);
            unsigned long long a2[8];
#pragma unroll
            for (int i = 0; i < 4; ++i) {
                float2 v = xrow[i];
                a2[2 * i]     = pack2(v.x, v.x);
                a2[2 * i + 1] = pack2(v.y, v.y);
            }
            const unsigned long long* wg2 =
                (const unsigned long long*)(sWg + k * LDS_W + tn * 4);
            const unsigned long long* wu2 =
                (const unsigned long long*)(sWu + k * LDS_W + tn * 4);
            unsigned long long g0 = wg2[0], g1 = wg2[1];
            unsigned long long u0 = wu2[0], u1 = wu2[1];
#pragma unroll
            for (int m = 0; m < 8; ++m) {
                accg[m][0] = ffma2(a2[m], g0, accg[m][0]);
                accg[m][1] = ffma2(a2[m], g1, accg[m][1]);
                accu[m][0] = ffma2(a2[m], u0, accu[m][0]);
                accu[m][1] = ffma2(a2[m], u1, accu[m][1]);
            }
        }
    }

    // epilogue: signs, silu, mul, down prescale -> d_hd
    const int nb = n0 + tn * 4;
    float4 gs4 = *(const float4*)(gsl + nb);
    float4 us4 = *(const float4*)(usl + nb);
    float4 ds4 = *(const float4*)(dsr + nb);
#pragma unroll
    for (int m = 0; m < 8; ++m) {
        int b = tm * 8 + m;
        float2 g0 = unpack2(accg[m][0]);
        float2 g1 = unpack2(accg[m][1]);
        float2 u0 = unpack2(accu[m][0]);
        float2 u1 = unpack2(accu[m][1]);
        float g[4] = {g0.x * gs4.x, g0.y * gs4.y, g1.x * gs4.z, g1.y * gs4.w};
        float u[4] = {u0.x * us4.x, u0.y * us4.y, u1.x * us4.z, u1.y * us4.w};
        float ds[4] = {ds4.x, ds4.y, ds4.z, ds4.w};
        float4 o;
        float* op = (float*)&o;
#pragma unroll
        for (int j = 0; j < 4; ++j) {
            float sg = g[j] / (1.0f + expf(-g[j]));
            op[j] = sg * u[j] * ds[j] * WSCALE;
        }
        *(float4*)(d_hd + (size_t)b * IDIM + nb) = o;
    }
}

// ---------- stage 2: down dequant-GEMM with split-K, atomic accumulate ----------
__global__ __launch_bounds__(NTHREADS)
void down_kernel(const int* __restrict__ walks, const float* __restrict__ lut,
                 const float* __restrict__ dsl, float* __restrict__ out) {
    __shared__ float sLut[NLUT];
    __shared__ float sX[BK * LDS_X];
    __shared__ float sW[BK * LDS_W];

    const int tid = threadIdx.x;
    {
        const float4* l4 = (const float4*)lut;
        float4* s4 = (float4*)sLut;
#pragma unroll
        for (int r = 0; r < NLUT / 4 / NTHREADS; ++r)
            s4[tid + r * NTHREADS] = l4[tid + r * NTHREADS];
    }

    const int n0 = blockIdx.x * BN;
    const int kBeg = blockIdx.y * (IDIM / SPLITK);
    const int kEnd = kBeg + (IDIM / SPLITK);
    const int tn = tid & 15;
    const int tm = tid >> 4;

    unsigned long long acc[8][2];
#pragma unroll
    for (int m = 0; m < 8; ++m) { acc[m][0] = 0ull; acc[m][1] = 0ull; }

    for (int k0 = kBeg; k0 < kEnd; k0 += BK) {
        __syncthreads();

#pragma unroll
        for (int r = 0; r < 4; ++r) {
            int idx = tid + r * NTHREADS;
            int m   = idx >> 3;
            int kq  = (idx & 7) << 2;
            float4 v = *(const float4*)(d_hd + (size_t)m * IDIM + k0 + kq);
            sX[(kq + 0) * LDS_X + m] = v.x;
            sX[(kq + 1) * LDS_X + m] = v.y;
            sX[(kq + 2) * LDS_X + m] = v.z;
            sX[(kq + 3) * LDS_X + m] = v.w;
        }
#pragma unroll
        for (int r = 0; r < 4; ++r) {
            int idx = tid + r * NTHREADS;
            int row = idx >> 3;
            int kq  = (idx & 7) << 2;
            int4 w = *(const int4*)(walks + (size_t)(n0 + row) * IDIM + k0 + kq);
            sW[(kq + 0) * LDS_W + row] = sLut[w.x];
            sW[(kq + 1) * LDS_W + row] = sLut[w.y];
            sW[(kq + 2) * LDS_W + row] = sLut[w.z];
            sW[(kq + 3) * LDS_W + row] = sLut[w.w];
        }
        __syncthreads();

#pragma unroll 4
        for (int k = 0; k < BK; ++k) {
            const float2* xrow = (const float2*)(sX + k * LDS_X + tm * 8);
            unsigned long long a2[8];
#pragma unroll
            for (int i = 0; i < 4; ++i) {
                float2 v = xrow[i];
                a2[2 * i]     = pack2(v.x, v.x);
                a2[2 * i + 1] = pack2(v.y, v.y);
            }
            const unsigned long long* w2 =
                (const unsigned long long*)(sW + k * LDS_W + tn * 4);
            unsigned long long w0 = w2[0], w1 = w2[1];
#pragma unroll
            for (int m = 0; m < 8; ++m) {
                acc[m][0] = ffma2(a2[m], w0, acc[m][0]);
                acc[m][1] = ffma2(a2[m], w1, acc[m][1]);
            }
        }
    }

    const int nb = n0 + tn * 4;
    float4 sl4 = *(const float4*)(dsl + nb);
#pragma unroll
    for (int m = 0; m < 8; ++m) {
        int b = tm * 8 + m;
        float2 p0 = unpack2(acc[m][0]);
        float2 p1 = unpack2(acc[m][1]);
        atomicAdd(out + (size_t)b * HDIM + nb + 0, p0.x * sl4.x);
        atomicAdd(out + (size_t)b * HDIM + nb + 1, p0.y * sl4.y);
        atomicAdd(out + (size_t)b * HDIM + nb + 2, p1.x * sl4.z);
        atomicAdd(out + (size_t)b * HDIM + nb + 3, p1.y * sl4.w);
    }
}

extern "C" void kernel_launch(void* const* d_in, const int* in_sizes, int n_in,
                              void* d_out, int out_size) {
    const float* x         = (const float*)d_in[0];
    const float* lut_gate  = (const float*)d_in[1];
    const float* lut_up    = (const float*)d_in[2];
    const float* lut_down  = (const float*)d_in[3];
    const int*   gwalks    = (const int*)d_in[4];
    const int*   uwalks    = (const int*)d_in[5];
    const int*   dwalks    = (const int*)d_in[6];
    const float* gsl       = (const float*)d_in[7];
    const float* gsr       = (const float*)d_in[8];
    const float* usl       = (const float*)d_in[9];
    const float* usr       = (const float*)d_in[10];
    const float* dsl       = (const float*)d_in[11];
    const float* dsr       = (const float*)d_in[12];
    float* out = (float*)d_out;

    const int smem1 = (2 * NLUT + BK * LDS_X + 2 * BK * LDS_W) * (int)sizeof(float);
    cudaFuncSetAttribute(gateup_kernel,
                         cudaFuncAttributeMaxDynamicSharedMemorySize, smem1);

    prep_kernel<<<(BSZ * HDIM + 255) / 256, 256>>>(x, gsr, usr);
    cudaMemsetAsync(out, 0, (size_t)BSZ * HDIM * sizeof(float));
    gateup_kernel<<<IDIM / BN, NTHREADS, smem1>>>(gwalks, uwalks, lut_gate, lut_up,
                                                  gsl, usl, dsr);
    down_kernel<<<dim3(HDIM / BN, SPLITK), NTHREADS>>>(dwalks, lut_down, dsl, out);
}

// round 3
// speedup vs baseline: 1.7447x; 1.7447x over previous
#include <cuda_runtime.h>
#include <math.h>

// Problem constants
#define BSZ   64
#define HDIM  4096
#define IDIM  14336
#define NLUT  4096
#define WSCALE 0.02f

// Tiling
#define BM 64
#define BN 64
#define BK 32
#define NTHREADS 128
#define PAD 2
#define LDS_W (BN + PAD)   // 66
#define LDS_X (BM + PAD)   // 66
#define SKG 4              // split-K for gate/up GEMM over HDIM
#define KSLICE_G (HDIM / SKG)    // 1024
#define SKD 14             // split-K for down GEMM over IDIM
#define KSLICE_D (IDIM / SKD)    // 1024

// Scratch (static device arrays; no allocations allowed)
__device__ float d_xg[BSZ * HDIM];            // x * gate_sign_r * WSCALE
__device__ float d_ratio[HDIM];               // gate_sign_r * up_sign_r
__device__ float d_hd[BSZ * IDIM];            // silu(gate)*up * down_sign_r * WSCALE
__device__ float d_gpart[SKG * BSZ * IDIM];   // gate partial sums per K-slice
__device__ float d_upart[SKG * BSZ * IDIM];   // up partial sums per K-slice

// ---------- packed fp32x2 helpers ----------
__device__ __forceinline__ unsigned long long ffma2(unsigned long long a,
                                                    unsigned long long b,
                                                    unsigned long long c) {
    unsigned long long r;
    asm("fma.rn.f32x2 %0, %1, %2, %3;" : "=l"(r) : "l"(a), "l"(b), "l"(c));
    return r;
}
__device__ __forceinline__ unsigned long long pack2(float lo, float hi) {
    unsigned long long r;
    asm("mov.b64 %0, {%1, %2};" : "=l"(r) : "f"(lo), "f"(hi));
    return r;
}
__device__ __forceinline__ float2 unpack2(unsigned long long d) {
    float2 f;
    asm("mov.b64 {%0, %1}, %2;" : "=f"(f.x), "=f"(f.y) : "l"(d));
    return f;
}

// ---------- prep: xg = x * gsr * scale ; ratio = gsr * usr ----------
__global__ void prep_kernel(const float* __restrict__ x,
                            const float* __restrict__ gsr,
                            const float* __restrict__ usr) {
    int idx = blockIdx.x * blockDim.x + threadIdx.x;
    if (idx < BSZ * HDIM) {
        int h = idx & (HDIM - 1);
        d_xg[idx] = x[idx] * gsr[h] * WSCALE;
    }
    if (idx < HDIM) {
        d_ratio[idx] = gsr[idx] * usr[idx];
    }
}

// ---------- stage 1: gate+up dequant-GEMM, split-K, partial outputs ----------
__global__ __launch_bounds__(NTHREADS, 3)
void gateup_kernel(const int* __restrict__ gwalks, const int* __restrict__ uwalks,
                   const float* __restrict__ lutg, const float* __restrict__ lutu) {
    extern __shared__ float smem[];
    float* sLutG = smem;
    float* sLutU = sLutG + NLUT;
    float* sX    = sLutU + NLUT;
    float* sWg   = sX + BK * LDS_X;
    float* sWu   = sWg + BK * LDS_W;

    const int tid = threadIdx.x;

    // cooperative LUT load
    {
        const float4* lg4 = (const float4*)lutg;
        const float4* lu4 = (const float4*)lutu;
        float4* sg4 = (float4*)sLutG;
        float4* su4 = (float4*)sLutU;
#pragma unroll
        for (int r = 0; r < NLUT / 4 / NTHREADS; ++r) {
            sg4[tid + r * NTHREADS] = lg4[tid + r * NTHREADS];
            su4[tid + r * NTHREADS] = lu4[tid + r * NTHREADS];
        }
    }

    const int n0 = blockIdx.x * BN;
    const int kBeg = blockIdx.y * KSLICE_G;
    const int tn = tid & 15;
    const int tm = tid >> 4;

    // loader lane geometry (same for all tiles)
    int lrow[4], lkq[4];
#pragma unroll
    for (int r = 0; r < 4; ++r) {
        int idx = tid + r * NTHREADS;
        lrow[r] = idx >> 3;
        lkq[r]  = (idx & 7) << 2;
    }

    // prefetch first walks tile into registers
    int4 pg[4], pu[4];
#pragma unroll
    for (int r = 0; r < 4; ++r) {
        size_t off = (size_t)(n0 + lrow[r]) * HDIM + kBeg + lkq[r];
        pg[r] = *(const int4*)(gwalks + off);
        pu[r] = *(const int4*)(uwalks + off);
    }

    unsigned long long accg[8][2], accu[8][2];
#pragma unroll
    for (int m = 0; m < 8; ++m) {
        accg[m][0] = 0ull; accg[m][1] = 0ull;
        accu[m][0] = 0ull; accu[m][1] = 0ull;
    }

    const int ntiles = KSLICE_G / BK;   // 32
    for (int t = 0; t < ntiles; ++t) {
        const int k0 = kBeg + t * BK;

        // issue X loads early (L2-resident)
        float4 xv[4];
#pragma unroll
        for (int r = 0; r < 4; ++r)
            xv[r] = *(const float4*)(d_xg + lrow[r] * HDIM + k0 + lkq[r]);

        __syncthreads();   // previous compute done (also orders LUT load @t=0)

        // X tile -> sX[k][m] transposed
#pragma unroll
        for (int r = 0; r < 4; ++r) {
            int m  = lrow[r];
            int kq = lkq[r];
            sX[(kq + 0) * LDS_X + m] = xv[r].x;
            sX[(kq + 1) * LDS_X + m] = xv[r].y;
            sX[(kq + 2) * LDS_X + m] = xv[r].z;
            sX[(kq + 3) * LDS_X + m] = xv[r].w;
        }

        // dequant from prefetched walks
#pragma unroll
        for (int r = 0; r < 4; ++r) {
            int row = lrow[r];
            int kq  = lkq[r];
            sWg[(kq + 0) * LDS_W + row] = sLutG[pg[r].x];
            sWg[(kq + 1) * LDS_W + row] = sLutG[pg[r].y];
            sWg[(kq + 2) * LDS_W + row] = sLutG[pg[r].z];
            sWg[(kq + 3) * LDS_W + row] = sLutG[pg[r].w];
            float4 rr = *(const float4*)(d_ratio + k0 + kq);
            sWu[(kq + 0) * LDS_W + row] = sLutU[pu[r].x] * rr.x;
            sWu[(kq + 1) * LDS_W + row] = sLutU[pu[r].y] * rr.y;
            sWu[(kq + 2) * LDS_W + row] = sLutU[pu[r].z] * rr.z;
            sWu[(kq + 3) * LDS_W + row] = sLutU[pu[r].w] * rr.w;
        }
        __syncthreads();

        // prefetch next walks tile (overlaps with compute below)
        if (t + 1 < ntiles) {
            const int kn = k0 + BK;
#pragma unroll
            for (int r = 0; r < 4; ++r) {
                size_t off = (size_t)(n0 + lrow[r]) * HDIM + kn + lkq[r];
                pg[r] = *(const int4*)(gwalks + off);
                pu[r] = *(const int4*)(uwalks + off);
            }
        }

#pragma unroll 4
        for (int k = 0; k < BK; ++k) {
            const float2* xrow = (const float2*)(sX + k * LDS_X + tm * 8);
            unsigned long long a2[8];
#pragma unroll
            for (int i = 0; i < 4; ++i) {
                float2 v = xrow[i];
                a2[2 * i]     = pack2(v.x, v.x);
                a2[2 * i + 1] = pack2(v.y, v.y);
            }
            const unsigned long long* wg2 =
                (const unsigned long long*)(sWg + k * LDS_W + tn * 4);
            const unsigned long long* wu2 =
                (const unsigned long long*)(sWu + k * LDS_W + tn * 4);
            unsigned long long g0 = wg2[0], g1 = wg2[1];
            unsigned long long u0 = wu2[0], u1 = wu2[1];
#pragma unroll
            for (int m = 0; m < 8; ++m) {
                accg[m][0] = ffma2(a2[m], g0, accg[m][0]);
                accg[m][1] = ffma2(a2[m], g1, accg[m][1]);
                accu[m][0] = ffma2(a2[m], u0, accu[m][0]);
                accu[m][1] = ffma2(a2[m], u1, accu[m][1]);
            }
        }
    }

    // write raw partial sums (non-atomic; each CTA owns its slice)
    const int nb = n0 + tn * 4;
    float* gp = d_gpart + (size_t)blockIdx.y * BSZ * IDIM;
    float* up = d_upart + (size_t)blockIdx.y * BSZ * IDIM;
#pragma unroll
    for (int m = 0; m < 8; ++m) {
        int b = tm * 8 + m;
        float2 g0 = unpack2(accg[m][0]);
        float2 g1 = unpack2(accg[m][1]);
        float2 u0 = unpack2(accu[m][0]);
        float2 u1 = unpack2(accu[m][1]);
        float4 go = {g0.x, g0.y, g1.x, g1.y};
        float4 uo = {u0.x, u0.y, u1.x, u1.y};
        *(float4*)(gp + (size_t)b * IDIM + nb) = go;
        *(float4*)(up + (size_t)b * IDIM + nb) = uo;
    }
}

// ---------- stage 1b: reduce partials + silu*mul epilogue -> d_hd ----------
__global__ void hd_kernel(const float* __restrict__ gsl,
                          const float* __restrict__ usl,
                          const float* __restrict__ dsr) {
    int t = blockIdx.x * blockDim.x + threadIdx.x;   // over BSZ*IDIM/4
    int b = t / (IDIM / 4);
    int i = (t - b * (IDIM / 4)) * 4;
    size_t off = (size_t)b * IDIM + i;

    float4 g = {0.f, 0.f, 0.f, 0.f}, u = {0.f, 0.f, 0.f, 0.f};
#pragma unroll
    for (int s = 0; s < SKG; ++s) {
        size_t po = (size_t)s * BSZ * IDIM + off;
        float4 gv = *(const float4*)(d_gpart + po);
        float4 uv = *(const float4*)(d_upart + po);
        g.x += gv.x; g.y += gv.y; g.z += gv.z; g.w += gv.w;
        u.x += uv.x; u.y += uv.y; u.z += uv.z; u.w += uv.w;
    }
    float4 gl = *(const float4*)(gsl + i);
    float4 ul = *(const float4*)(usl + i);
    float4 dr = *(const float4*)(dsr + i);
    float gg[4] = {g.x * gl.x, g.y * gl.y, g.z * gl.z, g.w * gl.w};
    float uu[4] = {u.x * ul.x, u.y * ul.y, u.z * ul.z, u.w * ul.w};
    float dd[4] = {dr.x, dr.y, dr.z, dr.w};
    float4 o;
    float* op = (float*)&o;
#pragma unroll
    for (int j = 0; j < 4; ++j) {
        float sg = gg[j] / (1.0f + __expf(-gg[j]));
        op[j] = sg * uu[j] * dd[j] * WSCALE;
    }
    *(float4*)(d_hd + off) = o;
}

// ---------- stage 2: down dequant-GEMM, split-K + atomics ----------
__global__ __launch_bounds__(NTHREADS, 4)
void down_kernel(const int* __restrict__ walks, const float* __restrict__ lut,
                 const float* __restrict__ dsl, float* __restrict__ out) {
    __shared__ float sLut[NLUT];
    __shared__ float sX[BK * LDS_X];
    __shared__ float sW[BK * LDS_W];

    const int tid = threadIdx.x;
    {
        const float4* l4 = (const float4*)lut;
        float4* s4 = (float4*)sLut;
#pragma unroll
        for (int r = 0; r < NLUT / 4 / NTHREADS; ++r)
            s4[tid + r * NTHREADS] = l4[tid + r * NTHREADS];
    }

    const int n0 = blockIdx.x * BN;
    const int kBeg = blockIdx.y * KSLICE_D;
    const int tn = tid & 15;
    const int tm = tid >> 4;

    int lrow[4], lkq[4];
#pragma unroll
    for (int r = 0; r < 4; ++r) {
        int idx = tid + r * NTHREADS;
        lrow[r] = idx >> 3;
        lkq[r]  = (idx & 7) << 2;
    }

    int4 pw[4];
#pragma unroll
    for (int r = 0; r < 4; ++r)
        pw[r] = *(const int4*)(walks + (size_t)(n0 + lrow[r]) * IDIM + kBeg + lkq[r]);

    unsigned long long acc[8][2];
#pragma unroll
    for (int m = 0; m < 8; ++m) { acc[m][0] = 0ull; acc[m][1] = 0ull; }

    const int ntiles = KSLICE_D / BK;   // 32
    for (int t = 0; t < ntiles; ++t) {
        const int k0 = kBeg + t * BK;

        float4 xv[4];
#pragma unroll
        for (int r = 0; r < 4; ++r)
            xv[r] = *(const float4*)(d_hd + (size_t)lrow[r] * IDIM + k0 + lkq[r]);

        __syncthreads();

#pragma unroll
        for (int r = 0; r < 4; ++r) {
            int m  = lrow[r];
            int kq = lkq[r];
            sX[(kq + 0) * LDS_X + m] = xv[r].x;
            sX[(kq + 1) * LDS_X + m] = xv[r].y;
            sX[(kq + 2) * LDS_X + m] = xv[r].z;
            sX[(kq + 3) * LDS_X + m] = xv[r].w;
        }
#pragma unroll
        for (int r = 0; r < 4; ++r) {
            int row = lrow[r];
            int kq  = lkq[r];
            sW[(kq + 0) * LDS_W + row] = sLut[pw[r].x];
            sW[(kq + 1) * LDS_W + row] = sLut[pw[r].y];
            sW[(kq + 2) * LDS_W + row] = sLut[pw[r].z];
            sW[(kq + 3) * LDS_W + row] = sLut[pw[r].w];
        }
        __syncthreads();

        if (t + 1 < ntiles) {
            const int kn = k0 + BK;
#pragma unroll
            for (int r = 0; r < 4; ++r)
                pw[r] = *(const int4*)(walks + (size_t)(n0 + lrow[r]) * IDIM + kn + lkq[r]);
        }

#pragma unroll 4
        for (int k = 0; k < BK; ++k) {
            const float2* xrow = (const float2*)(sX + k * LDS_X + tm * 8);
            unsigned long long a2[8];
#pragma unroll
            for (int i = 0; i < 4; ++i) {
                float2 v = xrow[i];
                a2[2 * i]     = pack2(v.x, v.x);
                a2[2 * i + 1] = pack2(v.y, v.y);
            }
            const unsigned long long* w2 =
                (const unsigned long long*)(sW + k * LDS_W + tn * 4);
            unsigned long long w0 = w2[0], w1 = w2[1];
#pragma unroll
            for (int m = 0; m < 8; ++m) {
                acc[m][0] = ffma2(a2[m], w0, acc[m][0]);
                acc[m][1] = ffma2(a2[m], w1, acc[m][1]);
            }
        }
    }

    const int nb = n0 + tn * 4;
    float4 sl4 = *(const float4*)(dsl + nb);
#pragma unroll
    for (int m = 0; m < 8; ++m) {
        int b = tm * 8 + m;
        float2 p0 = unpack2(acc[m][0]);
        float2 p1 = unpack2(acc[m][1]);
        atomicAdd(out + (size_t)b * HDIM + nb + 0, p0.x * sl4.x);
        atomicAdd(out + (size_t)b * HDIM + nb + 1, p0.y * sl4.y);
        atomicAdd(out + (size_t)b * HDIM + nb + 2, p1.x * sl4.z);
        atomicAdd(out + (size_t)b * HDIM + nb + 3, p1.y * sl4.w);
    }
}

extern "C" void kernel_launch(void* const* d_in, const int* in_sizes, int n_in,
                              void* d_out, int out_size) {
    const float* x         = (const float*)d_in[0];
    const float* lut_gate  = (const float*)d_in[1];
    const float* lut_up    = (const float*)d_in[2];
    const float* lut_down  = (const float*)d_in[3];
    const int*   gwalks    = (const int*)d_in[4];
    const int*   uwalks    = (const int*)d_in[5];
    const int*   dwalks    = (const int*)d_in[6];
    const float* gsl       = (const float*)d_in[7];
    const float* gsr       = (const float*)d_in[8];
    const float* usl       = (const float*)d_in[9];
    const float* usr       = (const float*)d_in[10];
    const float* dsl       = (const float*)d_in[11];
    const float* dsr       = (const float*)d_in[12];
    float* out = (float*)d_out;

    const int smem1 = (2 * NLUT + BK * LDS_X + 2 * BK * LDS_W) * (int)sizeof(float);
    cudaFuncSetAttribute(gateup_kernel,
                         cudaFuncAttributeMaxDynamicSharedMemorySize, smem1);

    prep_kernel<<<(BSZ * HDIM + 255) / 256, 256>>>(x, gsr, usr);
    cudaMemsetAsync(out, 0, (size_t)BSZ * HDIM * sizeof(float));
    gateup_kernel<<<dim3(IDIM / BN, SKG), NTHREADS, smem1>>>(gwalks, uwalks,
                                                             lut_gate, lut_up);
    hd_kernel<<<(BSZ * IDIM / 4) / 256, 256>>>(gsl, usl, dsr);
    down_kernel<<<dim3(HDIM / BN, SKD), NTHREADS>>>(dwalks, lut_down, dsl, out);
}

// round 5
// speedup vs baseline: 4.1435x; 2.3749x over previous
#include <cuda_runtime.h>
#include <cuda_fp16.h>
#include <math.h>
#include <stdint.h>

// Problem constants
#define BSZ   64
#define HDIM  4096
#define IDIM  14336
#define NLUT  4096
#define WSCALE 0.02f

#define NTHREADS 256
#define BK 64                  // K per tile (64 fp16 = 128B row)
#define TM 128                 // weight rows per CTA tile
#define SKG 4                  // split-K gate/up over HDIM
#define KSLICE_G (HDIM / SKG)  // 1024 -> 16 tiles
#define NT_G (KSLICE_G / BK)
#define SKD 28                 // split-K down over IDIM
#define KSLICE_D (IDIM / SKD)  // 512 -> 8 tiles
#define NT_D (KSLICE_D / BK)

#define SW128(o) ((o) ^ ((((uint32_t)(o)) >> 3) & 0x70))

// ---- scratch (static device arrays; no allocations) ----
__device__ __half d_xgh[BSZ * HDIM];                     // fp16(x * gsr * WSCALE)
__device__ __half d_xuh[BSZ * HDIM];                     // fp16(x * usr * WSCALE)
__device__ __half d_lgh[NLUT];                           // fp16 lut_gate
__device__ __half d_luh[NLUT];                           // fp16 lut_up
__device__ __half d_ldh[NLUT];                           // fp16(lut_down * WSCALE)
__device__ float  d_gpart[(size_t)SKG * IDIM * BSZ];     // [slice][i][b]
__device__ float  d_upart[(size_t)SKG * IDIM * BSZ];
__device__ float  d_dpart[(size_t)SKD * HDIM * BSZ];     // [slice][h][b]
__device__ __half d_hdh[BSZ * IDIM];                     // hidden fp16 [b][i]

// ---------------- PTX helpers (baseline ISA only) ----------------
__device__ __forceinline__ uint32_t smem_u32(const void* p) {
    uint32_t a;
    asm("{ .reg .u64 t; cvta.to.shared.u64 t, %1; cvt.u32.u64 %0, t; }" : "=r"(a) : "l"(p));
    return a;
}

__device__ __forceinline__ void ldmx4(uint32_t* r, uint32_t addr) {
    asm volatile("ldmatrix.sync.aligned.m8n8.x4.shared.b16 {%0,%1,%2,%3}, [%4];"
                 : "=r"(r[0]), "=r"(r[1]), "=r"(r[2]), "=r"(r[3]) : "r"(addr));
}

__device__ __forceinline__ void mma16816(float* c, const uint32_t* a,
                                         uint32_t b0, uint32_t b1) {
    asm volatile(
        "mma.sync.aligned.m16n8k16.row.col.f32.f16.f16.f32 "
        "{%0,%1,%2,%3}, {%4,%5,%6,%7}, {%8,%9}, {%0,%1,%2,%3};"
        : "+f"(c[0]), "+f"(c[1]), "+f"(c[2]), "+f"(c[3])
        : "r"(a[0]), "r"(a[1]), "r"(a[2]), "r"(a[3]), "r"(b0), "r"(b1));
}

// ---------------- prep ----------------
__global__ void prep_kernel(const float* __restrict__ x,
                            const float* __restrict__ gsr,
                            const float* __restrict__ usr,
                            const float* __restrict__ lg,
                            const float* __restrict__ lu,
                            const float* __restrict__ ld) {
    int idx = blockIdx.x * blockDim.x + threadIdx.x;
    if (idx < BSZ * HDIM) {
        int h = idx & (HDIM - 1);
        float xv = x[idx];
        d_xgh[idx] = __float2half(xv * gsr[h] * WSCALE);
        d_xuh[idx] = __float2half(xv * usr[h] * WSCALE);
    }
    if (idx < NLUT) {
        d_lgh[idx] = __float2half(lg[idx]);
        d_luh[idx] = __float2half(lu[idx]);
        d_ldh[idx] = __float2half(ld[idx] * WSCALE);  // fold WSCALE into down LUT
    }
}

// ---------------- tile loaders ----------------
// dequant: 128 rows x 64 codes -> fp16 SW128 tile (1024 16B chunks, 4/thread)
__device__ __forceinline__ void dequant_tile(const int* __restrict__ walks,
                                             int rowStride, int row0, int k0,
                                             const __half* __restrict__ lut,
                                             char* sA, int tid) {
#pragma unroll
    for (int g = 0; g < 4; ++g) {
        int chunk = tid + g * NTHREADS;
        int row = chunk >> 3;
        int cc = chunk & 7;
        const int4* p = (const int4*)(walks + (size_t)(row0 + row) * rowStride + k0 + cc * 8);
        int4 a = p[0], b = p[1];
        __half2 h0 = __halves2half2(lut[a.x], lut[a.y]);
        __half2 h1 = __halves2half2(lut[a.z], lut[a.w]);
        __half2 h2 = __halves2half2(lut[b.x], lut[b.y]);
        __half2 h3 = __halves2half2(lut[b.z], lut[b.w]);
        uint32_t off = row * 128 + cc * 16;
        uint4 v;
        v.x = *(uint32_t*)&h0; v.y = *(uint32_t*)&h1;
        v.z = *(uint32_t*)&h2; v.w = *(uint32_t*)&h3;
        *(uint4*)(sA + SW128(off)) = v;
    }
}

// X tile: 64 rows x 64 fp16 -> SW128 (512 chunks, 2/thread)
__device__ __forceinline__ void xload_tile(const __half* __restrict__ xsrc,
                                           int rowStride, int k0, char* sX, int tid) {
#pragma unroll
    for (int it = 0; it < 2; ++it) {
        int idx = tid + it * NTHREADS;
        int row = idx >> 3;
        int c = idx & 7;
        uint4 v = *(const uint4*)(xsrc + (size_t)row * rowStride + k0 + c * 8);
        uint32_t off = row * 128 + c * 16;
        *(uint4*)(sX + SW128(off)) = v;
    }
}

// ---------------- core GEMM tile compute ----------------
// acc[mi][nj][4]; Ab[2], Bb[2] are swizzled lane base addresses; addr = base ^ (ks<<5)
__device__ __forceinline__ void tile_mma(const uint32_t* Ab, const uint32_t* Bb,
                                         float acc[2][4][4]) {
#pragma unroll
    for (int ks = 0; ks < 4; ++ks) {
        uint32_t x = (uint32_t)(ks << 5);
        uint32_t a[2][4];
        ldmx4(a[0], Ab[0] ^ x);
        ldmx4(a[1], Ab[1] ^ x);
#pragma unroll
        for (int nb = 0; nb < 2; ++nb) {
            uint32_t r[4];
            ldmx4(r, Bb[nb] ^ x);
#pragma unroll
            for (int mi = 0; mi < 2; ++mi) {
                mma16816(acc[mi][2 * nb + 0], a[mi], r[0], r[1]);
                mma16816(acc[mi][2 * nb + 1], a[mi], r[2], r[3]);
            }
        }
    }
}

// lane geometry -> swizzled base addresses
__device__ __forceinline__ void make_bases(uint32_t sAb, uint32_t sXb,
                                           int mw, int nw, int lane,
                                           uint32_t* Ab, uint32_t* Bb) {
#pragma unroll
    for (int mi = 0; mi < 2; ++mi) {
        int row = mw + mi * 16 + (lane & 15);
        uint32_t off = (uint32_t)(row * 128 + (lane >> 4) * 16);
        Ab[mi] = sAb + SW128(off);
    }
#pragma unroll
    for (int nb = 0; nb < 2; ++nb) {
        int row = nw + nb * 16 + (lane & 7) + ((lane >> 4) << 3);
        uint32_t off = (uint32_t)(row * 128 + ((lane >> 3) & 1) * 16);
        Bb[nb] = sXb + SW128(off);
    }
}

// epilogue: write C fragments to partials laid out [row][b] (row-major, 64 b cols)
__device__ __forceinline__ void store_parts(float* part, int r0, int mw, int nw,
                                            int lane, float acc[2][4][4]) {
#pragma unroll
    for (int mi = 0; mi < 2; ++mi) {
        int row = r0 + mw + mi * 16 + (lane >> 2);
#pragma unroll
        for (int nj = 0; nj < 4; ++nj) {
            int bc = nw + nj * 8 + (lane & 3) * 2;
            float2 v0 = {acc[mi][nj][0], acc[mi][nj][1]};
            float2 v1 = {acc[mi][nj][2], acc[mi][nj][3]};
            *(float2*)(part + (size_t)row * BSZ + bc) = v0;
            *(float2*)(part + (size_t)(row + 8) * BSZ + bc) = v1;
        }
    }
}

// ---------------- gate/up GEMM (blockIdx.z: 0=gate, 1=up) ----------------
__global__ __launch_bounds__(NTHREADS, 3)
void gateup_kernel(const int* __restrict__ gwalks, const int* __restrict__ uwalks) {
    __shared__ __half sLut[NLUT];
    __shared__ __align__(128) char sA[TM * 128];
    __shared__ __align__(128) char sX[BSZ * 128];

    const int tid = threadIdx.x;
    const int lane = tid & 31;
    const int wid = tid >> 5;
    const int z = blockIdx.z;

    const int* walks = z ? uwalks : gwalks;
    const __half* lutg = z ? d_luh : d_lgh;
    const __half* xsrc = z ? d_xuh : d_xgh;

    {   // LUT -> smem
        const uint4* l4 = (const uint4*)lutg;
        uint4* s4 = (uint4*)sLut;
        s4[tid] = l4[tid];
        s4[tid + NTHREADS] = l4[tid + NTHREADS];
    }

    const int mw = (wid & 3) * 32;
    const int nw = (wid >> 2) * 32;
    uint32_t Ab[2], Bb[2];
    make_bases(smem_u32(sA), smem_u32(sX), mw, nw, lane, Ab, Bb);

    float acc[2][4][4];
#pragma unroll
    for (int mi = 0; mi < 2; ++mi)
#pragma unroll
        for (int nj = 0; nj < 4; ++nj)
#pragma unroll
            for (int q = 0; q < 4; ++q) acc[mi][nj][q] = 0.f;

    const int i0 = blockIdx.x * TM;
    const int kBeg = blockIdx.y * KSLICE_G;

    for (int t = 0; t < NT_G; ++t) {
        const int k0 = kBeg + t * BK;
        __syncthreads();                       // previous tile fully consumed
        dequant_tile(walks, HDIM, i0, k0, sLut, sA, tid);
        xload_tile(xsrc, HDIM, k0, sX, tid);
        __syncthreads();
        tile_mma(Ab, Bb, acc);
    }

    float* part = (z ? d_upart : d_gpart) + (size_t)blockIdx.y * ((size_t)IDIM * BSZ);
    store_parts(part, i0, mw, nw, lane, acc);
}

// ---------------- reduce gate/up partials + silu*mul -> fp16 hidden ----------------
__global__ void hd_kernel(const float* __restrict__ gsl,
                          const float* __restrict__ usl,
                          const float* __restrict__ dsr) {
    int t = blockIdx.x * blockDim.x + threadIdx.x;   // IDIM*16 threads
    int i = t >> 4;
    int bq = (t & 15) * 4;
    size_t off = (size_t)i * BSZ + bq;

    float4 g = {0.f, 0.f, 0.f, 0.f}, u = {0.f, 0.f, 0.f, 0.f};
#pragma unroll
    for (int s = 0; s < SKG; ++s) {
        size_t po = (size_t)s * ((size_t)IDIM * BSZ) + off;
        float4 gv = *(const float4*)(d_gpart + po);
        float4 uv = *(const float4*)(d_upart + po);
        g.x += gv.x; g.y += gv.y; g.z += gv.z; g.w += gv.w;
        u.x += uv.x; u.y += uv.y; u.z += uv.z; u.w += uv.w;
    }
    float gl = gsl[i], ul = usl[i], dr = dsr[i];
    float gg[4] = {g.x * gl, g.y * gl, g.z * gl, g.w * gl};
    float uu[4] = {u.x * ul, u.y * ul, u.z * ul, u.w * ul};
#pragma unroll
    for (int j = 0; j < 4; ++j) {
        float sg = gg[j] / (1.0f + __expf(-gg[j]));
        d_hdh[(size_t)(bq + j) * IDIM + i] = __float2half(sg * uu[j] * dr);
    }
}

// ---------------- down GEMM ----------------
__global__ __launch_bounds__(NTHREADS, 3)
void down_kernel(const int* __restrict__ walks) {
    __shared__ __half sLut[NLUT];
    __shared__ __align__(128) char sA[TM * 128];
    __shared__ __align__(128) char sX[BSZ * 128];

    const int tid = threadIdx.x;
    const int lane = tid & 31;
    const int wid = tid >> 5;

    {
        const uint4* l4 = (const uint4*)d_ldh;
        uint4* s4 = (uint4*)sLut;
        s4[tid] = l4[tid];
        s4[tid + NTHREADS] = l4[tid + NTHREADS];
    }

    const int mw = (wid & 3) * 32;
    const int nw = (wid >> 2) * 32;
    uint32_t Ab[2], Bb[2];
    make_bases(smem_u32(sA), smem_u32(sX), mw, nw, lane, Ab, Bb);

    float acc[2][4][4];
#pragma unroll
    for (int mi = 0; mi < 2; ++mi)
#pragma unroll
        for (int nj = 0; nj < 4; ++nj)
#pragma unroll
            for (int q = 0; q < 4; ++q) acc[mi][nj][q] = 0.f;

    const int h0 = blockIdx.x * TM;
    const int kBeg = blockIdx.y * KSLICE_D;

    for (int t = 0; t < NT_D; ++t) {
        const int k0 = kBeg + t * BK;
        __syncthreads();
        dequant_tile(walks, IDIM, h0, k0, sLut, sA, tid);
        xload_tile(d_hdh, IDIM, k0, sX, tid);
        __syncthreads();
        tile_mma(Ab, Bb, acc);
    }

    float* part = d_dpart + (size_t)blockIdx.y * ((size_t)HDIM * BSZ);
    store_parts(part, h0, mw, nw, lane, acc);
}

// ---------------- reduce down partials -> out ----------------
__global__ void dreduce_kernel(const float* __restrict__ dsl, float* __restrict__ out) {
    int t = blockIdx.x * blockDim.x + threadIdx.x;   // HDIM*16 threads
    int h = t >> 4;
    int bq = (t & 15) * 4;
    size_t off = (size_t)h * BSZ + bq;

    float4 a = {0.f, 0.f, 0.f, 0.f};
#pragma unroll
    for (int s = 0; s < SKD; ++s) {
        float4 v = *(const float4*)(d_dpart + (size_t)s * ((size_t)HDIM * BSZ) + off);
        a.x += v.x; a.y += v.y; a.z += v.z; a.w += v.w;
    }
    float sc = dsl[h];
    out[(size_t)(bq + 0) * HDIM + h] = a.x * sc;
    out[(size_t)(bq + 1) * HDIM + h] = a.y * sc;
    out[(size_t)(bq + 2) * HDIM + h] = a.z * sc;
    out[(size_t)(bq + 3) * HDIM + h] = a.w * sc;
}

// ---------------- launch ----------------
extern "C" void kernel_launch(void* const* d_in, const int* in_sizes, int n_in,
                              void* d_out, int out_size) {
    const float* x        = (const float*)d_in[0];
    const float* lut_gate = (const float*)d_in[1];
    const float* lut_up   = (const float*)d_in[2];
    const float* lut_down = (const float*)d_in[3];
    const int*   gwalks   = (const int*)d_in[4];
    const int*   uwalks   = (const int*)d_in[5];
    const int*   dwalks   = (const int*)d_in[6];
    const float* gsl      = (const float*)d_in[7];
    // gsr = d_in[8]
    const float* usl      = (const float*)d_in[9];
    // usr = d_in[10]
    const float* dsl      = (const float*)d_in[11];
    const float* dsr      = (const float*)d_in[12];
    const float* gsr      = (const float*)d_in[8];
    const float* usr      = (const float*)d_in[10];
    float* out = (float*)d_out;

    prep_kernel<<<(BSZ * HDIM + 255) / 256, 256>>>(x, gsr, usr, lut_gate, lut_up, lut_down);
    gateup_kernel<<<dim3(IDIM / TM, SKG, 2), NTHREADS>>>(gwalks, uwalks);
    hd_kernel<<<(IDIM * 16) / 256, 256>>>(gsl, usl, dsr);
    down_kernel<<<dim3(HDIM / TM, SKD), NTHREADS>>>(dwalks);
    dreduce_kernel<<<(HDIM * 16) / 256, 256>>>(dsl, out);
}

// round 6
// speedup vs baseline: 4.1493x; 1.0014x over previous
#include <cuda_runtime.h>
#include <cuda_fp16.h>
#include <math.h>
#include <stdint.h>

// Problem constants
#define BSZ   64
#define HDIM  4096
#define IDIM  14336
#define NLUT  4096
#define WSCALE 0.02f

#define NTHREADS 256
#define BK 64                  // K per tile (64 fp16 = 128B row)
#define TM 128                 // weight rows per CTA tile
#define SKG 4                  // split-K gate/up over HDIM
#define KSLICE_G (HDIM / SKG)  // 1024 -> 16 tiles
#define NT_G (KSLICE_G / BK)
#define SKD 28                 // split-K down over IDIM
#define KSLICE_D (IDIM / SKD)  // 512 -> 8 tiles
#define NT_D (KSLICE_D / BK)

#define SW128(o) ((o) ^ ((((uint32_t)(o)) >> 3) & 0x70))

// ---- scratch (static device arrays; no allocations) ----
__device__ __half d_xgh[BSZ * HDIM];                     // fp16(x * gsr * WSCALE)
__device__ __half d_xuh[BSZ * HDIM];                     // fp16(x * usr * WSCALE)
__device__ __half d_lgh[NLUT];                           // fp16 lut_gate
__device__ __half d_luh[NLUT];                           // fp16 lut_up
__device__ __half d_ldh[NLUT];                           // fp16(lut_down * WSCALE)
__device__ float  d_gpart[(size_t)SKG * IDIM * BSZ];     // [slice][i][b]
__device__ float  d_upart[(size_t)SKG * IDIM * BSZ];
__device__ float  d_dpart[(size_t)SKD * HDIM * BSZ];     // [slice][h][b]
__device__ __half d_hdh[BSZ * IDIM];                     // hidden fp16 [b][i]

// ---------------- PTX helpers (baseline ISA only) ----------------
__device__ __forceinline__ uint32_t smem_u32(const void* p) {
    uint32_t a;
    asm("{ .reg .u64 t; cvta.to.shared.u64 t, %1; cvt.u32.u64 %0, t; }" : "=r"(a) : "l"(p));
    return a;
}

__device__ __forceinline__ void ldmx4(uint32_t* r, uint32_t addr) {
    asm volatile("ldmatrix.sync.aligned.m8n8.x4.shared.b16 {%0,%1,%2,%3}, [%4];"
                 : "=r"(r[0]), "=r"(r[1]), "=r"(r[2]), "=r"(r[3]) : "r"(addr));
}

__device__ __forceinline__ void mma16816(float* c, const uint32_t* a,
                                         uint32_t b0, uint32_t b1) {
    asm volatile(
        "mma.sync.aligned.m16n8k16.row.col.f32.f16.f16.f32 "
        "{%0,%1,%2,%3}, {%4,%5,%6,%7}, {%8,%9}, {%0,%1,%2,%3};"
        : "+f"(c[0]), "+f"(c[1]), "+f"(c[2]), "+f"(c[3])
        : "r"(a[0]), "r"(a[1]), "r"(a[2]), "r"(a[3]), "r"(b0), "r"(b1));
}

// ---------------- prep ----------------
__global__ void prep_kernel(const float* __restrict__ x,
                            const float* __restrict__ gsr,
                            const float* __restrict__ usr,
                            const float* __restrict__ lg,
                            const float* __restrict__ lu,
                            const float* __restrict__ ld) {
    int idx = blockIdx.x * blockDim.x + threadIdx.x;
    if (idx < BSZ * HDIM) {
        int h = idx & (HDIM - 1);
        float xv = x[idx];
        d_xgh[idx] = __float2half(xv * gsr[h] * WSCALE);
        d_xuh[idx] = __float2half(xv * usr[h] * WSCALE);
    }
    if (idx < NLUT) {
        d_lgh[idx] = __float2half(lg[idx]);
        d_luh[idx] = __float2half(lu[idx]);
        d_ldh[idx] = __float2half(ld[idx] * WSCALE);  // fold WSCALE into down LUT
    }
}

// ---------------- tile loaders ----------------
// dequant: 128 rows x 64 codes -> fp16 SW128 tile (1024 16B chunks, 4/thread)
__device__ __forceinline__ void dequant_tile(const int* __restrict__ walks,
                                             int rowStride, int row0, int k0,
                                             const __half* __restrict__ lut,
                                             char* sA, int tid) {
#pragma unroll
    for (int g = 0; g < 4; ++g) {
        int chunk = tid + g * NTHREADS;
        int row = chunk >> 3;
        int cc = chunk & 7;
        const int4* p = (const int4*)(walks + (size_t)(row0 + row) * rowStride + k0 + cc * 8);
        int4 a = p[0], b = p[1];
        __half2 h0 = __halves2half2(lut[a.x], lut[a.y]);
        __half2 h1 = __halves2half2(lut[a.z], lut[a.w]);
        __half2 h2 = __halves2half2(lut[b.x], lut[b.y]);
        __half2 h3 = __halves2half2(lut[b.z], lut[b.w]);
        uint32_t off = row * 128 + cc * 16;
        uint4 v;
        v.x = *(uint32_t*)&h0; v.y = *(uint32_t*)&h1;
        v.z = *(uint32_t*)&h2; v.w = *(uint32_t*)&h3;
        *(uint4*)(sA + SW128(off)) = v;
    }
}

// X tile: 64 rows x 64 fp16 -> SW128 (512 chunks, 2/thread)
__device__ __forceinline__ void xload_tile(const __half* __restrict__ xsrc,
                                           int rowStride, int k0, char* sX, int tid) {
#pragma unroll
    for (int it = 0; it < 2; ++it) {
        int idx = tid + it * NTHREADS;
        int row = idx >> 3;
        int c = idx & 7;
        uint4 v = *(const uint4*)(xsrc + (size_t)row * rowStride + k0 + c * 8);
        uint32_t off = row * 128 + c * 16;
        *(uint4*)(sX + SW128(off)) = v;
    }
}

// ---------------- core GEMM tile compute ----------------
// acc[mi][nj][4]; Ab[2], Bb[2] are swizzled lane base addresses; addr = base ^ (ks<<5)
__device__ __forceinline__ void tile_mma(const uint32_t* Ab, const uint32_t* Bb,
                                         float acc[2][4][4]) {
#pragma unroll
    for (int ks = 0; ks < 4; ++ks) {
        uint32_t x = (uint32_t)(ks << 5);
        uint32_t a[2][4];
        ldmx4(a[0], Ab[0] ^ x);
        ldmx4(a[1], Ab[1] ^ x);
#pragma unroll
        for (int nb = 0; nb < 2; ++nb) {
            uint32_t r[4];
            ldmx4(r, Bb[nb] ^ x);
#pragma unroll
            for (int mi = 0; mi < 2; ++mi) {
                mma16816(acc[mi][2 * nb + 0], a[mi], r[0], r[1]);
                mma16816(acc[mi][2 * nb + 1], a[mi], r[2], r[3]);
            }
        }
    }
}

// lane geometry -> swizzled base addresses
__device__ __forceinline__ void make_bases(uint32_t sAb, uint32_t sXb,
                                           int mw, int nw, int lane,
                                           uint32_t* Ab, uint32_t* Bb) {
#pragma unroll
    for (int mi = 0; mi < 2; ++mi) {
        int row = mw + mi * 16 + (lane & 15);
        uint32_t off = (uint32_t)(row * 128 + (lane >> 4) * 16);
        Ab[mi] = sAb + SW128(off);
    }
#pragma unroll
    for (int nb = 0; nb < 2; ++nb) {
        int row = nw + nb * 16 + (lane & 7) + ((lane >> 4) << 3);
        uint32_t off = (uint32_t)(row * 128 + ((lane >> 3) & 1) * 16);
        Bb[nb] = sXb + SW128(off);
    }
}

// epilogue: write C fragments to partials laid out [row][b] (row-major, 64 b cols)
__device__ __forceinline__ void store_parts(float* part, int r0, int mw, int nw,
                                            int lane, float acc[2][4][4]) {
#pragma unroll
    for (int mi = 0; mi < 2; ++mi) {
        int row = r0 + mw + mi * 16 + (lane >> 2);
#pragma unroll
        for (int nj = 0; nj < 4; ++nj) {
            int bc = nw + nj * 8 + (lane & 3) * 2;
            float2 v0 = {acc[mi][nj][0], acc[mi][nj][1]};
            float2 v1 = {acc[mi][nj][2], acc[mi][nj][3]};
            *(float2*)(part + (size_t)row * BSZ + bc) = v0;
            *(float2*)(part + (size_t)(row + 8) * BSZ + bc) = v1;
        }
    }
}

// ---------------- gate/up GEMM (blockIdx.z: 0=gate, 1=up) ----------------
__global__ __launch_bounds__(NTHREADS, 3)
void gateup_kernel(const int* __restrict__ gwalks, const int* __restrict__ uwalks) {
    __shared__ __half sLut[NLUT];
    __shared__ __align__(128) char sA[TM * 128];
    __shared__ __align__(128) char sX[BSZ * 128];

    const int tid = threadIdx.x;
    const int lane = tid & 31;
    const int wid = tid >> 5;
    const int z = blockIdx.z;

    const int* walks = z ? uwalks : gwalks;
    const __half* lutg = z ? d_luh : d_lgh;
    const __half* xsrc = z ? d_xuh : d_xgh;

    {   // LUT -> smem
        const uint4* l4 = (const uint4*)lutg;
        uint4* s4 = (uint4*)sLut;
        s4[tid] = l4[tid];
        s4[tid + NTHREADS] = l4[tid + NTHREADS];
    }

    const int mw = (wid & 3) * 32;
    const int nw = (wid >> 2) * 32;
    uint32_t Ab[2], Bb[2];
    make_bases(smem_u32(sA), smem_u32(sX), mw, nw, lane, Ab, Bb);

    float acc[2][4][4];
#pragma unroll
    for (int mi = 0; mi < 2; ++mi)
#pragma unroll
        for (int nj = 0; nj < 4; ++nj)
#pragma unroll
            for (int q = 0; q < 4; ++q) acc[mi][nj][q] = 0.f;

    const int i0 = blockIdx.x * TM;
    const int kBeg = blockIdx.y * KSLICE_G;

    for (int t = 0; t < NT_G; ++t) {
        const int k0 = kBeg + t * BK;
        __syncthreads();                       // previous tile fully consumed
        dequant_tile(walks, HDIM, i0, k0, sLut, sA, tid);
        xload_tile(xsrc, HDIM, k0, sX, tid);
        __syncthreads();
        tile_mma(Ab, Bb, acc);
    }

    float* part = (z ? d_upart : d_gpart) + (size_t)blockIdx.y * ((size_t)IDIM * BSZ);
    store_parts(part, i0, mw, nw, lane, acc);
}

// ---------------- reduce gate/up partials + silu*mul -> fp16 hidden ----------------
__global__ void hd_kernel(const float* __restrict__ gsl,
                          const float* __restrict__ usl,
                          const float* __restrict__ dsr) {
    int t = blockIdx.x * blockDim.x + threadIdx.x;   // IDIM*16 threads
    int i = t >> 4;
    int bq = (t & 15) * 4;
    size_t off = (size_t)i * BSZ + bq;

    float4 g = {0.f, 0.f, 0.f, 0.f}, u = {0.f, 0.f, 0.f, 0.f};
#pragma unroll
    for (int s = 0; s < SKG; ++s) {
        size_t po = (size_t)s * ((size_t)IDIM * BSZ) + off;
        float4 gv = *(const float4*)(d_gpart + po);
        float4 uv = *(const float4*)(d_upart + po);
        g.x += gv.x; g.y += gv.y; g.z += gv.z; g.w += gv.w;
        u.x += uv.x; u.y += uv.y; u.z += uv.z; u.w += uv.w;
    }
    float gl = gsl[i], ul = usl[i], dr = dsr[i];
    float gg[4] = {g.x * gl, g.y * gl, g.z * gl, g.w * gl};
    float uu[4] = {u.x * ul, u.y * ul, u.z * ul, u.w * ul};
#pragma unroll
    for (int j = 0; j < 4; ++j) {
        float sg = gg[j] / (1.0f + __expf(-gg[j]));
        d_hdh[(size_t)(bq + j) * IDIM + i] = __float2half(sg * uu[j] * dr);
    }
}

// ---------------- down GEMM ----------------
__global__ __launch_bounds__(NTHREADS, 3)
void down_kernel(const int* __restrict__ walks) {
    __shared__ __half sLut[NLUT];
    __shared__ __align__(128) char sA[TM * 128];
    __shared__ __align__(128) char sX[BSZ * 128];

    const int tid = threadIdx.x;
    const int lane = tid & 31;
    const int wid = tid >> 5;

    {
        const uint4* l4 = (const uint4*)d_ldh;
        uint4* s4 = (uint4*)sLut;
        s4[tid] = l4[tid];
        s4[tid + NTHREADS] = l4[tid + NTHREADS];
    }

    const int mw = (wid & 3) * 32;
    const int nw = (wid >> 2) * 32;
    uint32_t Ab[2], Bb[2];
    make_bases(smem_u32(sA), smem_u32(sX), mw, nw, lane, Ab, Bb);

    float acc[2][4][4];
#pragma unroll
    for (int mi = 0; mi < 2; ++mi)
#pragma unroll
        for (int nj = 0; nj < 4; ++nj)
#pragma unroll
            for (int q = 0; q < 4; ++q) acc[mi][nj][q] = 0.f;

    const int h0 = blockIdx.x * TM;
    const int kBeg = blockIdx.y * KSLICE_D;

    for (int t = 0; t < NT_D; ++t) {
        const int k0 = kBeg + t * BK;
        __syncthreads();
        dequant_tile(walks, IDIM, h0, k0, sLut, sA, tid);
        xload_tile(d_hdh, IDIM, k0, sX, tid);
        __syncthreads();
        tile_mma(Ab, Bb, acc);
    }

    float* part = d_dpart + (size_t)blockIdx.y * ((size_t)HDIM * BSZ);
    store_parts(part, h0, mw, nw, lane, acc);
}

// ---------------- reduce down partials -> out ----------------
__global__ void dreduce_kernel(const float* __restrict__ dsl, float* __restrict__ out) {
    int t = blockIdx.x * blockDim.x + threadIdx.x;   // HDIM*16 threads
    int h = t >> 4;
    int bq = (t & 15) * 4;
    size_t off = (size_t)h * BSZ + bq;

    float4 a = {0.f, 0.f, 0.f, 0.f};
#pragma unroll
    for (int s = 0; s < SKD; ++s) {
        float4 v = *(const float4*)(d_dpart + (size_t)s * ((size_t)HDIM * BSZ) + off);
        a.x += v.x; a.y += v.y; a.z += v.z; a.w += v.w;
    }
    float sc = dsl[h];
    out[(size_t)(bq + 0) * HDIM + h] = a.x * sc;
    out[(size_t)(bq + 1) * HDIM + h] = a.y * sc;
    out[(size_t)(bq + 2) * HDIM + h] = a.z * sc;
    out[(size_t)(bq + 3) * HDIM + h] = a.w * sc;
}

// ---------------- launch ----------------
extern "C" void kernel_launch(void* const* d_in, const int* in_sizes, int n_in,
                              void* d_out, int out_size) {
    const float* x        = (const float*)d_in[0];
    const float* lut_gate = (const float*)d_in[1];
    const float* lut_up   = (const float*)d_in[2];
    const float* lut_down = (const float*)d_in[3];
    const int*   gwalks   = (const int*)d_in[4];
    const int*   uwalks   = (const int*)d_in[5];
    const int*   dwalks   = (const int*)d_in[6];
    const float* gsl      = (const float*)d_in[7];
    // gsr = d_in[8]
    const float* usl      = (const float*)d_in[9];
    // usr = d_in[10]
    const float* dsl      = (const float*)d_in[11];
    const float* dsr      = (const float*)d_in[12];
    const float* gsr      = (const float*)d_in[8];
    const float* usr      = (const float*)d_in[10];
    float* out = (float*)d_out;

    prep_kernel<<<(BSZ * HDIM + 255) / 256, 256>>>(x, gsr, usr, lut_gate, lut_up, lut_down);
    gateup_kernel<<<dim3(IDIM / TM, SKG, 2), NTHREADS>>>(gwalks, uwalks);
    hd_kernel<<<(IDIM * 16) / 256, 256>>>(gsl, usl, dsr);
    down_kernel<<<dim3(HDIM / TM, SKD), NTHREADS>>>(dwalks);
    dreduce_kernel<<<(HDIM * 16) / 256, 256>>>(dsl, out);
}

// round 7
// speedup vs baseline: 4.1823x; 1.0079x over previous
#include <cuda_runtime.h>
#include <cuda_fp16.h>
#include <math.h>
#include <stdint.h>

// Problem constants
#define BSZ   64
#define HDIM  4096
#define IDIM  14336
#define NLUT  4096
#define WSCALE 0.02f

#define NTHREADS 256
#define BK 64                  // K per tile (64 fp16 = 128B row)
#define TM 128                 // weight rows per CTA tile
#define SKG 4                  // split-K gate/up over HDIM
#define KSLICE_G (HDIM / SKG)  // 1024 -> 16 tiles
#define NT_G (KSLICE_G / BK)
#define SKD 28                 // split-K down over IDIM
#define KSLICE_D (IDIM / SKD)  // 512 -> 8 tiles
#define NT_D (KSLICE_D / BK)

#define SW128(o) ((o) ^ ((((uint32_t)(o)) >> 3) & 0x70))

// ---- scratch (static device arrays; no allocations) ----
__device__ __half d_xgh[BSZ * HDIM];                     // fp16(x * gsr * WSCALE)
__device__ __half d_xuh[BSZ * HDIM];                     // fp16(x * usr * WSCALE)
__device__ __half d_lgh[NLUT];                           // fp16 lut_gate
__device__ __half d_luh[NLUT];                           // fp16 lut_up
__device__ __half d_ldh[NLUT];                           // fp16(lut_down * WSCALE)
__device__ float  d_gpart[(size_t)SKG * IDIM * BSZ];     // [slice][i][b]
__device__ float  d_upart[(size_t)SKG * IDIM * BSZ];
__device__ float  d_dpart[(size_t)SKD * HDIM * BSZ];     // [slice][h][b]
__device__ __half d_hdh[BSZ * IDIM];                     // hidden fp16 [b][i]

// ---------------- PTX helpers (baseline ISA only) ----------------
__device__ __forceinline__ uint32_t smem_u32(const void* p) {
    uint32_t a;
    asm("{ .reg .u64 t; cvta.to.shared.u64 t, %1; cvt.u32.u64 %0, t; }" : "=r"(a) : "l"(p));
    return a;
}

__device__ __forceinline__ void ldmx4(uint32_t* r, uint32_t addr) {
    asm volatile("ldmatrix.sync.aligned.m8n8.x4.shared.b16 {%0,%1,%2,%3}, [%4];"
                 : "=r"(r[0]), "=r"(r[1]), "=r"(r[2]), "=r"(r[3]) : "r"(addr));
}

__device__ __forceinline__ void mma16816(float* c, const uint32_t* a,
                                         uint32_t b0, uint32_t b1) {
    asm volatile(
        "mma.sync.aligned.m16n8k16.row.col.f32.f16.f16.f32 "
        "{%0,%1,%2,%3}, {%4,%5,%6,%7}, {%8,%9}, {%0,%1,%2,%3};"
        : "+f"(c[0]), "+f"(c[1]), "+f"(c[2]), "+f"(c[3])
        : "r"(a[0]), "r"(a[1]), "r"(a[2]), "r"(a[3]), "r"(b0), "r"(b1));
}

// ---------------- prep ----------------
__global__ void prep_kernel(const float* __restrict__ x,
                            const float* __restrict__ gsr,
                            const float* __restrict__ usr,
                            const float* __restrict__ lg,
                            const float* __restrict__ lu,
                            const float* __restrict__ ld) {
    int idx = blockIdx.x * blockDim.x + threadIdx.x;
    if (idx < BSZ * HDIM) {
        int h = idx & (HDIM - 1);
        float xv = x[idx];
        d_xgh[idx] = __float2half(xv * gsr[h] * WSCALE);
        d_xuh[idx] = __float2half(xv * usr[h] * WSCALE);
    }
    if (idx < NLUT) {
        d_lgh[idx] = __float2half(lg[idx]);
        d_luh[idx] = __float2half(lu[idx]);
        d_ldh[idx] = __float2half(ld[idx] * WSCALE);  // fold WSCALE into down LUT
    }
}

// ---------------- tile loaders ----------------
// dequant: 128 rows x 64 codes -> fp16 SW128 tile (1024 16B chunks, 4/thread)
__device__ __forceinline__ void dequant_tile(const int* __restrict__ walks,
                                             int rowStride, int row0, int k0,
                                             const __half* __restrict__ lut,
                                             char* sA, int tid) {
#pragma unroll
    for (int g = 0; g < 4; ++g) {
        int chunk = tid + g * NTHREADS;
        int row = chunk >> 3;
        int cc = chunk & 7;
        const int4* p = (const int4*)(walks + (size_t)(row0 + row) * rowStride + k0 + cc * 8);
        int4 a = p[0], b = p[1];
        __half2 h0 = __halves2half2(lut[a.x], lut[a.y]);
        __half2 h1 = __halves2half2(lut[a.z], lut[a.w]);
        __half2 h2 = __halves2half2(lut[b.x], lut[b.y]);
        __half2 h3 = __halves2half2(lut[b.z], lut[b.w]);
        uint32_t off = row * 128 + cc * 16;
        uint4 v;
        v.x = *(uint32_t*)&h0; v.y = *(uint32_t*)&h1;
        v.z = *(uint32_t*)&h2; v.w = *(uint32_t*)&h3;
        *(uint4*)(sA + SW128(off)) = v;
    }
}

// X tile: 64 rows x 64 fp16 -> SW128 (512 chunks, 2/thread)
__device__ __forceinline__ void xload_tile(const __half* __restrict__ xsrc,
                                           int rowStride, int k0, char* sX, int tid) {
#pragma unroll
    for (int it = 0; it < 2; ++it) {
        int idx = tid + it * NTHREADS;
        int row = idx >> 3;
        int c = idx & 7;
        uint4 v = *(const uint4*)(xsrc + (size_t)row * rowStride + k0 + c * 8);
        uint32_t off = row * 128 + c * 16;
        *(uint4*)(sX + SW128(off)) = v;
    }
}

// ---------------- core GEMM tile compute ----------------
// acc[mi][nj][4]; Ab[2], Bb[2] are swizzled lane base addresses; addr = base ^ (ks<<5)
__device__ __forceinline__ void tile_mma(const uint32_t* Ab, const uint32_t* Bb,
                                         float acc[2][4][4]) {
#pragma unroll
    for (int ks = 0; ks < 4; ++ks) {
        uint32_t x = (uint32_t)(ks << 5);
        uint32_t a[2][4];
        ldmx4(a[0], Ab[0] ^ x);
        ldmx4(a[1], Ab[1] ^ x);
#pragma unroll
        for (int nb = 0; nb < 2; ++nb) {
            uint32_t r[4];
            ldmx4(r, Bb[nb] ^ x);
#pragma unroll
            for (int mi = 0; mi < 2; ++mi) {
                mma16816(acc[mi][2 * nb + 0], a[mi], r[0], r[1]);
                mma16816(acc[mi][2 * nb + 1], a[mi], r[2], r[3]);
            }
        }
    }
}

// lane geometry -> swizzled base addresses
__device__ __forceinline__ void make_bases(uint32_t sAb, uint32_t sXb,
                                           int mw, int nw, int lane,
                                           uint32_t* Ab, uint32_t* Bb) {
#pragma unroll
    for (int mi = 0; mi < 2; ++mi) {
        int row = mw + mi * 16 + (lane & 15);
        uint32_t off = (uint32_t)(row * 128 + (lane >> 4) * 16);
        Ab[mi] = sAb + SW128(off);
    }
#pragma unroll
    for (int nb = 0; nb < 2; ++nb) {
        int row = nw + nb * 16 + (lane & 7) + ((lane >> 4) << 3);
        uint32_t off = (uint32_t)(row * 128 + ((lane >> 3) & 1) * 16);
        Bb[nb] = sXb + SW128(off);
    }
}

// epilogue: write C fragments to partials laid out [row][b] (row-major, 64 b cols)
__device__ __forceinline__ void store_parts(float* part, int r0, int mw, int nw,
                                            int lane, float acc[2][4][4]) {
#pragma unroll
    for (int mi = 0; mi < 2; ++mi) {
        int row = r0 + mw + mi * 16 + (lane >> 2);
#pragma unroll
        for (int nj = 0; nj < 4; ++nj) {
            int bc = nw + nj * 8 + (lane & 3) * 2;
            float2 v0 = {acc[mi][nj][0], acc[mi][nj][1]};
            float2 v1 = {acc[mi][nj][2], acc[mi][nj][3]};
            *(float2*)(part + (size_t)row * BSZ + bc) = v0;
            *(float2*)(part + (size_t)(row + 8) * BSZ + bc) = v1;
        }
    }
}

// ---------------- gate/up GEMM (blockIdx.z: 0=gate, 1=up) ----------------
__global__ __launch_bounds__(NTHREADS, 3)
void gateup_kernel(const int* __restrict__ gwalks, const int* __restrict__ uwalks) {
    __shared__ __half sLut[NLUT];
    __shared__ __align__(128) char sA[TM * 128];
    __shared__ __align__(128) char sX[BSZ * 128];

    const int tid = threadIdx.x;
    const int lane = tid & 31;
    const int wid = tid >> 5;
    const int z = blockIdx.z;

    const int* walks = z ? uwalks : gwalks;
    const __half* lutg = z ? d_luh : d_lgh;
    const __half* xsrc = z ? d_xuh : d_xgh;

    {   // LUT -> smem
        const uint4* l4 = (const uint4*)lutg;
        uint4* s4 = (uint4*)sLut;
        s4[tid] = l4[tid];
        s4[tid + NTHREADS] = l4[tid + NTHREADS];
    }

    const int mw = (wid & 3) * 32;
    const int nw = (wid >> 2) * 32;
    uint32_t Ab[2], Bb[2];
    make_bases(smem_u32(sA), smem_u32(sX), mw, nw, lane, Ab, Bb);

    float acc[2][4][4];
#pragma unroll
    for (int mi = 0; mi < 2; ++mi)
#pragma unroll
        for (int nj = 0; nj < 4; ++nj)
#pragma unroll
            for (int q = 0; q < 4; ++q) acc[mi][nj][q] = 0.f;

    const int i0 = blockIdx.x * TM;
    const int kBeg = blockIdx.y * KSLICE_G;

    for (int t = 0; t < NT_G; ++t) {
        const int k0 = kBeg + t * BK;
        __syncthreads();                       // previous tile fully consumed
        dequant_tile(walks, HDIM, i0, k0, sLut, sA, tid);
        xload_tile(xsrc, HDIM, k0, sX, tid);
        __syncthreads();
        tile_mma(Ab, Bb, acc);
    }

    float* part = (z ? d_upart : d_gpart) + (size_t)blockIdx.y * ((size_t)IDIM * BSZ);
    store_parts(part, i0, mw, nw, lane, acc);
}

// ---------------- reduce gate/up partials + silu*mul -> fp16 hidden ----------------
__global__ void hd_kernel(const float* __restrict__ gsl,
                          const float* __restrict__ usl,
                          const float* __restrict__ dsr) {
    int t = blockIdx.x * blockDim.x + threadIdx.x;   // IDIM*16 threads
    int i = t >> 4;
    int bq = (t & 15) * 4;
    size_t off = (size_t)i * BSZ + bq;

    float4 g = {0.f, 0.f, 0.f, 0.f}, u = {0.f, 0.f, 0.f, 0.f};
#pragma unroll
    for (int s = 0; s < SKG; ++s) {
        size_t po = (size_t)s * ((size_t)IDIM * BSZ) + off;
        float4 gv = *(const float4*)(d_gpart + po);
        float4 uv = *(const float4*)(d_upart + po);
        g.x += gv.x; g.y += gv.y; g.z += gv.z; g.w += gv.w;
        u.x += uv.x; u.y += uv.y; u.z += uv.z; u.w += uv.w;
    }
    float gl = gsl[i], ul = usl[i], dr = dsr[i];
    float gg[4] = {g.x * gl, g.y * gl, g.z * gl, g.w * gl};
    float uu[4] = {u.x * ul, u.y * ul, u.z * ul, u.w * ul};
#pragma unroll
    for (int j = 0; j < 4; ++j) {
        float sg = gg[j] / (1.0f + __expf(-gg[j]));
        d_hdh[(size_t)(bq + j) * IDIM + i] = __float2half(sg * uu[j] * dr);
    }
}

// ---------------- down GEMM ----------------
__global__ __launch_bounds__(NTHREADS, 3)
void down_kernel(const int* __restrict__ walks) {
    __shared__ __half sLut[NLUT];
    __shared__ __align__(128) char sA[TM * 128];
    __shared__ __align__(128) char sX[BSZ * 128];

    const int tid = threadIdx.x;
    const int lane = tid & 31;
    const int wid = tid >> 5;

    {
        const uint4* l4 = (const uint4*)d_ldh;
        uint4* s4 = (uint4*)sLut;
        s4[tid] = l4[tid];
        s4[tid + NTHREADS] = l4[tid + NTHREADS];
    }

    const int mw = (wid & 3) * 32;
    const int nw = (wid >> 2) * 32;
    uint32_t Ab[2], Bb[2];
    make_bases(smem_u32(sA), smem_u32(sX), mw, nw, lane, Ab, Bb);

    float acc[2][4][4];
#pragma unroll
    for (int mi = 0; mi < 2; ++mi)
#pragma unroll
        for (int nj = 0; nj < 4; ++nj)
#pragma unroll
            for (int q = 0; q < 4; ++q) acc[mi][nj][q] = 0.f;

    const int h0 = blockIdx.x * TM;
    const int kBeg = blockIdx.y * KSLICE_D;

    for (int t = 0; t < NT_D; ++t) {
        const int k0 = kBeg + t * BK;
        __syncthreads();
        dequant_tile(walks, IDIM, h0, k0, sLut, sA, tid);
        xload_tile(d_hdh, IDIM, k0, sX, tid);
        __syncthreads();
        tile_mma(Ab, Bb, acc);
    }

    float* part = d_dpart + (size_t)blockIdx.y * ((size_t)HDIM * BSZ);
    store_parts(part, h0, mw, nw, lane, acc);
}

// ---------------- reduce down partials -> out ----------------
__global__ void dreduce_kernel(const float* __restrict__ dsl, float* __restrict__ out) {
    int t = blockIdx.x * blockDim.x + threadIdx.x;   // HDIM*16 threads
    int h = t >> 4;
    int bq = (t & 15) * 4;
    size_t off = (size_t)h * BSZ + bq;

    float4 a = {0.f, 0.f, 0.f, 0.f};
#pragma unroll
    for (int s = 0; s < SKD; ++s) {
        float4 v = *(const float4*)(d_dpart + (size_t)s * ((size_t)HDIM * BSZ) + off);
        a.x += v.x; a.y += v.y; a.z += v.z; a.w += v.w;
    }
    float sc = dsl[h];
    out[(size_t)(bq + 0) * HDIM + h] = a.x * sc;
    out[(size_t)(bq + 1) * HDIM + h] = a.y * sc;
    out[(size_t)(bq + 2) * HDIM + h] = a.z * sc;
    out[(size_t)(bq + 3) * HDIM + h] = a.w * sc;
}

// ---------------- launch ----------------
extern "C" void kernel_launch(void* const* d_in, const int* in_sizes, int n_in,
                              void* d_out, int out_size) {
    const float* x        = (const float*)d_in[0];
    const float* lut_gate = (const float*)d_in[1];
    const float* lut_up   = (const float*)d_in[2];
    const float* lut_down = (const float*)d_in[3];
    const int*   gwalks   = (const int*)d_in[4];
    const int*   uwalks   = (const int*)d_in[5];
    const int*   dwalks   = (const int*)d_in[6];
    const float* gsl      = (const float*)d_in[7];
    // gsr = d_in[8]
    const float* usl      = (const float*)d_in[9];
    // usr = d_in[10]
    const float* dsl      = (const float*)d_in[11];
    const float* dsr      = (const float*)d_in[12];
    const float* gsr      = (const float*)d_in[8];
    const float* usr      = (const float*)d_in[10];
    float* out = (float*)d_out;

    prep_kernel<<<(BSZ * HDIM + 255) / 256, 256>>>(x, gsr, usr, lut_gate, lut_up, lut_down);
    gateup_kernel<<<dim3(IDIM / TM, SKG, 2), NTHREADS>>>(gwalks, uwalks);
    hd_kernel<<<(IDIM * 16) / 256, 256>>>(gsl, usl, dsr);
    down_kernel<<<dim3(HDIM / TM, SKD), NTHREADS>>>(dwalks);
    dreduce_kernel<<<(HDIM * 16) / 256, 256>>>(dsl, out);
}